// round 1
// baseline (speedup 1.0000x reference)
#include <cuda_runtime.h>
#include <math.h>

#define T 1024
#define C 128
#define NB 16
#define LUP 523776          // T*(T-1)/2
#define NOUT 2046           // LUP / 256
#define LEAK 0.2f

// Scratch: packed upper-triangle distances per batch, and row squared norms.
__device__ float g_up[(size_t)NB * LUP];   // 33.5 MB
__device__ float g_xx[NB * T];

// ---------------------------------------------------------------------------
// Kernel 1: xx[b][i] = sum_c x[b][i][c]^2.  One warp per row.
// ---------------------------------------------------------------------------
__global__ __launch_bounds__(256) void xx_kernel(const float* __restrict__ x) {
    int warp = (blockIdx.x * 256 + threadIdx.x) >> 5;
    int lane = threadIdx.x & 31;
    if (warp >= NB * T) return;
    const float4* row = (const float4*)(x + (size_t)warp * C);
    float4 v = row[lane];
    float s = v.x * v.x + v.y * v.y + v.z * v.z + v.w * v.w;
    #pragma unroll
    for (int o = 16; o; o >>= 1) s += __shfl_xor_sync(0xffffffffu, s, o);
    if (lane == 0) g_xx[warp] = s;
}

// ---------------------------------------------------------------------------
// Kernel 2: upper-triangular tiles of the Gram matrix -> packed distances.
// 64x64 tile per block, K=128 split into two 64-phases (fits 48KB smem).
// Shared layout [m][k] with stride 68 floats (coalesced loads, ~2-way LDS).
// Micro-tile 4x4 per thread, interleaved mapping m=ty+16e, n=tx+16f.
// ---------------------------------------------------------------------------
#define TS 68   // padded shared row stride in floats

__global__ __launch_bounds__(256) void dist_kernel(const float* __restrict__ x) {
    __shared__ float As[64 * TS];
    __shared__ float Bs[64 * TS];

    int b = blockIdx.y;
    int t = blockIdx.x;
    // map linear tile id -> upper-triangular (ti, tj), 16x16 tile grid
    int ti = 0, rem = t;
    while (rem >= 16 - ti) { rem -= 16 - ti; ++ti; }
    int tj = ti + rem;
    int i0 = ti * 64, j0 = tj * 64;

    int tid = threadIdx.x;
    int tx = tid & 15, ty = tid >> 4;
    const float* xb = x + (size_t)b * T * C;

    float acc[4][4];
    #pragma unroll
    for (int e = 0; e < 4; ++e)
        #pragma unroll
        for (int f = 0; f < 4; ++f) acc[e][f] = 0.0f;

    for (int kp = 0; kp < 2; ++kp) {
        // load phase: 64 rows x 64 cols (16 float4/row), coalesced
        #pragma unroll
        for (int it = 0; it < 4; ++it) {
            int f4 = it * 256 + tid;          // 0..1023
            int kq = f4 & 15, m = f4 >> 4;    // kq: float4 col, m: row
            const float* src = xb + (size_t)(i0 + m) * C + kp * 64 + kq * 4;
            *(float4*)&As[m * TS + kq * 4] = *(const float4*)src;
            const float* srb = xb + (size_t)(j0 + m) * C + kp * 64 + kq * 4;
            *(float4*)&Bs[m * TS + kq * 4] = *(const float4*)srb;
        }
        __syncthreads();

        #pragma unroll 4
        for (int k = 0; k < 64; k += 4) {
            float4 a[4], u[4];
            #pragma unroll
            for (int e = 0; e < 4; ++e)
                a[e] = *(const float4*)&As[(ty + 16 * e) * TS + k];
            #pragma unroll
            for (int f = 0; f < 4; ++f)
                u[f] = *(const float4*)&Bs[(tx + 16 * f) * TS + k];
            #pragma unroll
            for (int e = 0; e < 4; ++e)
                #pragma unroll
                for (int f = 0; f < 4; ++f) {
                    acc[e][f] += a[e].x * u[f].x;
                    acc[e][f] += a[e].y * u[f].y;
                    acc[e][f] += a[e].z * u[f].z;
                    acc[e][f] += a[e].w * u[f].w;
                }
        }
        __syncthreads();
    }

    // epilogue: d = sqrt(max(xx_i + xx_j - 2*dot, 0)), write triu-packed
    float xxj[4];
    #pragma unroll
    for (int f = 0; f < 4; ++f) xxj[f] = g_xx[b * T + j0 + tx + 16 * f];

    #pragma unroll
    for (int e = 0; e < 4; ++e) {
        int i = i0 + ty + 16 * e;
        float xxi = g_xx[b * T + i];
        // pos(i,j) = i*(2T-1-i)/2 + (j - i - 1)
        long ro = (long)i * (2 * T - 1 - i) / 2 - i - 1;
        long basep = (long)b * LUP + ro;
        #pragma unroll
        for (int f = 0; f < 4; ++f) {
            int j = j0 + tx + 16 * f;
            if (j > i) {
                float d2 = xxi + xxj[f] - 2.0f * acc[e][f];
                g_up[basep + j] = sqrtf(fmaxf(d2, 0.0f));
            }
        }
    }
}

// ---------------------------------------------------------------------------
// Kernel 3: fused 8-layer conv stack. 6 output positions per block
// (2046 = 341 * 6), 1536 input distances per block, whole tree in smem.
// Buffers are channel-inner ([p][8]) so index math is shift/mask.
// wgt layout: [0,16) w0; [16,24) b0; [24,792) w1..w6 (128 each);
//             [792,840) b1..b6 (8 each); [840,856) w7; [856] b7.
// ---------------------------------------------------------------------------
__global__ __launch_bounds__(256) void conv_kernel(
    const float* __restrict__ w0, const float* __restrict__ b0,
    const float* __restrict__ w1, const float* __restrict__ b1,
    const float* __restrict__ w2, const float* __restrict__ b2,
    const float* __restrict__ w3, const float* __restrict__ b3,
    const float* __restrict__ w4, const float* __restrict__ b4,
    const float* __restrict__ w5, const float* __restrict__ b5,
    const float* __restrict__ w6, const float* __restrict__ b6,
    const float* __restrict__ w7, const float* __restrict__ b7,
    float* __restrict__ out)
{
    __shared__ float A[6144];    // up to 8ch x 768, channel-inner
    __shared__ float Bu[3072];   // up to 8ch x 384; also holds the 1536 inputs
    __shared__ float wgt[860];

    int tid = threadIdx.x;
    int b   = blockIdx.y;
    int blk = blockIdx.x;        // 0..340

    // ---- stage weights into shared ----
    if (tid < 128) {
        wgt[ 24 + tid] = w1[tid];
        wgt[152 + tid] = w2[tid];
        wgt[280 + tid] = w3[tid];
        wgt[408 + tid] = w4[tid];
        wgt[536 + tid] = w5[tid];
        wgt[664 + tid] = w6[tid];
    } else {
        int u = tid - 128;
        if (u < 16)       wgt[u]        = w0[u];
        else if (u < 24)  wgt[u]        = b0[u - 16];
        else if (u < 32)  wgt[792 + (u-24)] = b1[u-24];
        else if (u < 40)  wgt[800 + (u-32)] = b2[u-32];
        else if (u < 48)  wgt[808 + (u-40)] = b3[u-40];
        else if (u < 56)  wgt[816 + (u-48)] = b4[u-48];
        else if (u < 64)  wgt[824 + (u-56)] = b5[u-56];
        else if (u < 72)  wgt[832 + (u-64)] = b6[u-64];
        else if (u < 88)  wgt[840 + (u-72)] = w7[u-72];
        else if (u == 88) wgt[856]          = b7[0];
    }

    // ---- load 1536 contiguous packed distances into Bu ----
    {
        long gbase = (long)b * LUP + (long)blk * 1536;
        #pragma unroll
        for (int q = tid; q < 1536; q += 256) Bu[q] = g_up[gbase + q];
    }
    __syncthreads();

    // ---- layer 0: 1ch x 1536 -> 8ch x 768 (into A, channel-inner) ----
    for (int q = tid; q < 6144; q += 256) {
        int c = q & 7, p = q >> 3;
        float v = wgt[16 + c] + wgt[2*c] * Bu[2*p] + wgt[2*c + 1] * Bu[2*p + 1];
        A[p * 8 + c] = (v > 0.0f) ? v : LEAK * v;
    }
    __syncthreads();

    // ---- layers 1..6: 8ch -> 8ch, halving ----
    float* src = A;
    float* dst = Bu;
    int len = 768;
    for (int l = 0; l < 6; ++l) {
        int olen = len >> 1;
        const float* W  = wgt + 24 + l * 128;
        const float* BB = wgt + 792 + l * 8;
        for (int q = tid; q < 8 * olen; q += 256) {
            int c = q & 7, p = q >> 3;
            const float* s0 = src + 16 * p;     // rows 2p and 2p+1, 8ch each
            const float* wr = W + c * 16;
            float acc = BB[c];
            #pragma unroll
            for (int ci = 0; ci < 8; ++ci)
                acc += wr[2*ci] * s0[ci] + wr[2*ci + 1] * s0[8 + ci];
            dst[p * 8 + c] = (acc > 0.0f) ? acc : LEAK * acc;
        }
        __syncthreads();
        float* tmp = src; src = dst; dst = tmp;
        len = olen;
    }

    // ---- layer 7: 8ch x 12 -> 1ch x 6 (no activation) ----
    if (tid < 6) {
        int p = tid;
        const float* s0 = src + 16 * p;
        float acc = wgt[856];
        #pragma unroll
        for (int ci = 0; ci < 8; ++ci)
            acc += wgt[840 + 2*ci] * s0[ci] + wgt[841 + 2*ci] * s0[8 + ci];
        out[b * NOUT + blk * 6 + p] = acc;
    }
}

// ---------------------------------------------------------------------------
extern "C" void kernel_launch(void* const* d_in, const int* in_sizes, int n_in,
                              void* d_out, int out_size) {
    const float* x = (const float*)d_in[0];
    const float* w[8];
    const float* bb[8];
    for (int i = 0; i < 8; ++i) {
        w[i]  = (const float*)d_in[1 + 2 * i];
        bb[i] = (const float*)d_in[2 + 2 * i];
    }
    float* out = (float*)d_out;

    xx_kernel<<<(NB * T) / 8, 256>>>(x);
    dist_kernel<<<dim3(136, NB), 256>>>(x);
    conv_kernel<<<dim3(341, NB), 256>>>(
        w[0], bb[0], w[1], bb[1], w[2], bb[2], w[3], bb[3],
        w[4], bb[4], w[5], bb[5], w[6], bb[6], w[7], bb[7], out);
}

// round 3
// speedup vs baseline: 1.1711x; 1.1711x over previous
#include <cuda_runtime.h>
#include <math.h>
#include <stdint.h>

#define T 1024
#define C 128
#define NB 16
#define LUP 523776          // T*(T-1)/2
#define NOUT 2046           // LUP / 256
#define LEAK 0.2f

// ---------------------------------------------------------------------------
// Device globals (scratch)
// ---------------------------------------------------------------------------
__device__ float g_up[(size_t)NB * LUP];   // packed upper-triangle distances
__device__ float g_xx[NB * T];             // row squared norms

// ---------------------------------------------------------------------------
// Helpers
// ---------------------------------------------------------------------------
__device__ __forceinline__ uint32_t to_tf32(float f) {
    uint32_t r;
    asm("cvt.rna.tf32.f32 %0, %1;" : "=r"(r) : "f"(f));
    return r;
}

__device__ __forceinline__ void mma_tf32(float* d, const uint32_t* a, const uint32_t* b) {
    asm volatile(
        "mma.sync.aligned.m16n8k8.row.col.f32.tf32.tf32.f32 "
        "{%0,%1,%2,%3}, {%4,%5,%6,%7}, {%8,%9}, {%0,%1,%2,%3};"
        : "+f"(d[0]), "+f"(d[1]), "+f"(d[2]), "+f"(d[3])
        : "r"(a[0]), "r"(a[1]), "r"(a[2]), "r"(a[3]),
          "r"(b[0]), "r"(b[1]));
}

// ---------------------------------------------------------------------------
// Kernel 1: xx[b][i] = sum_c x[b][i][c]^2.  One warp per row.
// ---------------------------------------------------------------------------
__global__ __launch_bounds__(256) void xx_kernel(const float* __restrict__ x) {
    int warp = (blockIdx.x * 256 + threadIdx.x) >> 5;
    int lane = threadIdx.x & 31;
    if (warp >= NB * T) return;
    const float4* row = (const float4*)(x + (size_t)warp * C);
    float4 v = row[lane];
    float s = v.x * v.x + v.y * v.y + v.z * v.z + v.w * v.w;
    #pragma unroll
    for (int o = 16; o; o >>= 1) s += __shfl_xor_sync(0xffffffffu, s, o);
    if (lane == 0) g_xx[warp] = s;
}

// ---------------------------------------------------------------------------
// Kernel 2: tf32 mma.sync Gram tiles -> packed sqrt distances.
// 128x128 tile per block, upper-triangular 8x8 tile grid (36) x 16 batches.
// Warp tile 64x32 (warps arranged 2 x 4). Single tf32 pass, fp32 accumulate.
// Smem: As/Bs 128 rows x 128 k, padded stride 132 words (conflict-free frags).
// ---------------------------------------------------------------------------
#define AS_STRIDE 132
#define AS_BYTES  (128 * AS_STRIDE * 4)       // 67584
#define DIST_SMEM (2 * AS_BYTES)              // 135168

__global__ __launch_bounds__(256) void dist_kernel(const float* __restrict__ x) {
    extern __shared__ __align__(16) unsigned char sm[];
    uint32_t* As = (uint32_t*)sm;
    uint32_t* Bs = (uint32_t*)(sm + AS_BYTES);

    int tid = threadIdx.x;
    int wid = tid >> 5;
    int lane = tid & 31;
    int grp = lane >> 2;        // 0..7
    int tg  = lane & 3;         // 0..3

    int b = blockIdx.y;
    int t = blockIdx.x;
    int ti = 0, rem = t;
    while (rem >= 8 - ti) { rem -= 8 - ti; ++ti; }
    int tj = ti + rem;
    int i0 = ti * 128, j0 = tj * 128;

    const float* xb = x + (size_t)b * T * C;

    // ---- load + tf32-convert both tiles (coalesced float4, conflict-free STS) ----
    #pragma unroll
    for (int it = 0; it < 16; ++it) {
        int f4 = it * 256 + tid;           // 0..4095
        int row = f4 >> 5, c4 = f4 & 31;
        float4 va = *(const float4*)(xb + (size_t)(i0 + row) * C + c4 * 4);
        uint4 ta = make_uint4(to_tf32(va.x), to_tf32(va.y), to_tf32(va.z), to_tf32(va.w));
        *(uint4*)&As[row * AS_STRIDE + c4 * 4] = ta;
        float4 vb = *(const float4*)(xb + (size_t)(j0 + row) * C + c4 * 4);
        uint4 tb = make_uint4(to_tf32(vb.x), to_tf32(vb.y), to_tf32(vb.z), to_tf32(vb.w));
        *(uint4*)&Bs[row * AS_STRIDE + c4 * 4] = tb;
    }
    __syncthreads();

    // ---- mma mainloop ----
    int warp_m = (wid >> 2) * 64;          // 0 or 64
    int warp_n = (wid & 3) * 32;           // 0,32,64,96

    float acc[4][4][4];
    #pragma unroll
    for (int e = 0; e < 4; ++e)
        #pragma unroll
        for (int f = 0; f < 4; ++f)
            #pragma unroll
            for (int q = 0; q < 4; ++q) acc[e][f][q] = 0.0f;

    int abase = (warp_m + grp) * AS_STRIDE + tg;
    int bbase = (warp_n + grp) * AS_STRIDE + tg;

    #pragma unroll 2
    for (int kb = 0; kb < 128; kb += 8) {
        uint32_t a[4][4], bf[4][2];
        #pragma unroll
        for (int e = 0; e < 4; ++e) {
            int r = abase + 16 * e * AS_STRIDE + kb;
            a[e][0] = As[r];
            a[e][1] = As[r + 8 * AS_STRIDE];
            a[e][2] = As[r + 4];
            a[e][3] = As[r + 8 * AS_STRIDE + 4];
        }
        #pragma unroll
        for (int f = 0; f < 4; ++f) {
            int r = bbase + 8 * f * AS_STRIDE + kb;
            bf[f][0] = Bs[r];
            bf[f][1] = Bs[r + 4];
        }
        #pragma unroll
        for (int e = 0; e < 4; ++e)
            #pragma unroll
            for (int f = 0; f < 4; ++f)
                mma_tf32(acc[e][f], a[e], bf[f]);
    }

    // ---- epilogue: d = sqrt(max(xxi + xxj - 2g, 0)) -> staged transpose ----
    float xi[4][2], xj[4][2];
    #pragma unroll
    for (int e = 0; e < 4; ++e) {
        int il = warp_m + 16 * e + grp;
        xi[e][0] = g_xx[b * T + i0 + il];
        xi[e][1] = g_xx[b * T + i0 + il + 8];
    }
    #pragma unroll
    for (int f = 0; f < 4; ++f) {
        int jl = warp_n + 8 * f + 2 * tg;
        xj[f][0] = g_xx[b * T + j0 + jl];
        xj[f][1] = g_xx[b * T + j0 + jl + 1];
    }

    __syncthreads();   // done reading As/Bs; reuse As region as staging
    float* S = (float*)sm;   // 128 x stride-129

    #pragma unroll
    for (int e = 0; e < 4; ++e) {
        int il = warp_m + 16 * e + grp;
        #pragma unroll
        for (int f = 0; f < 4; ++f) {
            int jl = warp_n + 8 * f + 2 * tg;
            float d00 = fmaf(-2.0f, acc[e][f][0], xi[e][0] + xj[f][0]);
            float d01 = fmaf(-2.0f, acc[e][f][1], xi[e][0] + xj[f][1]);
            float d10 = fmaf(-2.0f, acc[e][f][2], xi[e][1] + xj[f][0]);
            float d11 = fmaf(-2.0f, acc[e][f][3], xi[e][1] + xj[f][1]);
            S[il * 129 + jl]           = sqrtf(fmaxf(d00, 0.0f));
            S[il * 129 + jl + 1]       = sqrtf(fmaxf(d01, 0.0f));
            S[(il + 8) * 129 + jl]     = sqrtf(fmaxf(d10, 0.0f));
            S[(il + 8) * 129 + jl + 1] = sqrtf(fmaxf(d11, 0.0f));
        }
    }
    __syncthreads();

    // ---- coalesced packed-triangle store ----
    {
        long bbase2 = (long)b * LUP;
        #pragma unroll
        for (int q = tid; q < 128 * 128; q += 256) {
            int m = q >> 7, jj = q & 127;
            int i2 = i0 + m, j2 = j0 + jj;
            if (j2 > i2) {
                long ro = (long)i2 * (2 * T - 1 - i2) / 2 - i2 - 1;
                g_up[bbase2 + ro + j2] = S[m * 129 + jj];
            }
        }
    }
}

// ---------------------------------------------------------------------------
// Kernel 3: fused 8-layer conv stack (verbatim from round-1 passing build).
// ---------------------------------------------------------------------------
__global__ __launch_bounds__(256) void conv_kernel(
    const float* __restrict__ w0, const float* __restrict__ b0,
    const float* __restrict__ w1, const float* __restrict__ b1,
    const float* __restrict__ w2, const float* __restrict__ b2,
    const float* __restrict__ w3, const float* __restrict__ b3,
    const float* __restrict__ w4, const float* __restrict__ b4,
    const float* __restrict__ w5, const float* __restrict__ b5,
    const float* __restrict__ w6, const float* __restrict__ b6,
    const float* __restrict__ w7, const float* __restrict__ b7,
    float* __restrict__ out)
{
    __shared__ float A[6144];
    __shared__ float Bu[3072];
    __shared__ float wgt[860];

    int tid = threadIdx.x;
    int b   = blockIdx.y;
    int blk = blockIdx.x;

    if (tid < 128) {
        wgt[ 24 + tid] = w1[tid];
        wgt[152 + tid] = w2[tid];
        wgt[280 + tid] = w3[tid];
        wgt[408 + tid] = w4[tid];
        wgt[536 + tid] = w5[tid];
        wgt[664 + tid] = w6[tid];
    } else {
        int u = tid - 128;
        if (u < 16)       wgt[u]        = w0[u];
        else if (u < 24)  wgt[u]        = b0[u - 16];
        else if (u < 32)  wgt[792 + (u-24)] = b1[u-24];
        else if (u < 40)  wgt[800 + (u-32)] = b2[u-32];
        else if (u < 48)  wgt[808 + (u-40)] = b3[u-40];
        else if (u < 56)  wgt[816 + (u-48)] = b4[u-48];
        else if (u < 64)  wgt[824 + (u-56)] = b5[u-56];
        else if (u < 72)  wgt[832 + (u-64)] = b6[u-64];
        else if (u < 88)  wgt[840 + (u-72)] = w7[u-72];
        else if (u == 88) wgt[856]          = b7[0];
    }

    {
        long gbase = (long)b * LUP + (long)blk * 1536;
        #pragma unroll
        for (int q = tid; q < 1536; q += 256) Bu[q] = g_up[gbase + q];
    }
    __syncthreads();

    for (int q = tid; q < 6144; q += 256) {
        int c = q & 7, p = q >> 3;
        float v = wgt[16 + c] + wgt[2*c] * Bu[2*p] + wgt[2*c + 1] * Bu[2*p + 1];
        A[p * 8 + c] = (v > 0.0f) ? v : LEAK * v;
    }
    __syncthreads();

    float* src = A;
    float* dst = Bu;
    int len = 768;
    for (int l = 0; l < 6; ++l) {
        int olen = len >> 1;
        const float* W  = wgt + 24 + l * 128;
        const float* BB = wgt + 792 + l * 8;
        for (int q = tid; q < 8 * olen; q += 256) {
            int c = q & 7, p = q >> 3;
            const float* s0 = src + 16 * p;
            const float* wr = W + c * 16;
            float acc = BB[c];
            #pragma unroll
            for (int ci = 0; ci < 8; ++ci)
                acc += wr[2*ci] * s0[ci] + wr[2*ci + 1] * s0[8 + ci];
            dst[p * 8 + c] = (acc > 0.0f) ? acc : LEAK * acc;
        }
        __syncthreads();
        float* tmp = src; src = dst; dst = tmp;
        len = olen;
    }

    if (tid < 6) {
        int p = tid;
        const float* s0 = src + 16 * p;
        float acc = wgt[856];
        #pragma unroll
        for (int ci = 0; ci < 8; ++ci)
            acc += wgt[840 + 2*ci] * s0[ci] + wgt[841 + 2*ci] * s0[8 + ci];
        out[b * NOUT + blk * 6 + p] = acc;
    }
}

// ---------------------------------------------------------------------------
extern "C" void kernel_launch(void* const* d_in, const int* in_sizes, int n_in,
                              void* d_out, int out_size) {
    const float* x = (const float*)d_in[0];
    const float* w[8];
    const float* bb[8];
    for (int i = 0; i < 8; ++i) {
        w[i]  = (const float*)d_in[1 + 2 * i];
        bb[i] = (const float*)d_in[2 + 2 * i];
    }
    float* out = (float*)d_out;

    static int smem_set = 0;
    if (!smem_set) {
        cudaFuncSetAttribute(dist_kernel,
                             cudaFuncAttributeMaxDynamicSharedMemorySize, DIST_SMEM);
        smem_set = 1;
    }

    xx_kernel<<<(NB * T) / 8, 256>>>(x);
    dist_kernel<<<dim3(36, NB), 256, DIST_SMEM>>>(x);
    conv_kernel<<<dim3(341, NB), 256>>>(
        w[0], bb[0], w[1], bb[1], w[2], bb[2], w[3], bb[3],
        w[4], bb[4], w[5], bb[5], w[6], bb[6], w[7], bb[7], out);
}